// round 14
// baseline (speedup 1.0000x reference)
#include <cuda_runtime.h>
#include <cuda_fp16.h>
#include <cstdint>

// Problem constants
#define TPAD  65656      // t_padded = T_SIM + T_KERNEL - 1
#define TOUT  65536      // output time samples
#define CCH   384        // channels
#define NROWS 768        // SIZE * C
#define NB    168        // number of OA blocks
#define HOP   392        // BLOCK - s2 + 1
#define S2    121        // kernel length
#define NFFT  512        // OA block size
#define NCHUNK 24
#define BLKS  7          // blocks per chunk: 24*7 = 168
#define NSTRIP (NCHUNK - 1)   // 23 boundary strips per row

// fp16 filtered signal y[row][t]
__device__ __align__(256) __half g_yhi[(size_t)NROWS * TOUT];
// chunk-boundary strip contributions
__device__ float g_bt[NROWS][NSTRIP][120];    // tail of block 7(s+1)-1
__device__ float g_bh[NROWS][NSTRIP][120];    // head of block 7(s+1)
// Precomputed W[d][c] = std[c]*vt[c][d] in fp16
__device__ __align__(256) __half g_Whi[CCH * CCH];
// FFT tables
__device__ float  g_kss[NFFT];        // symmetric-extended kernel_fft / 512
__device__ float2 g_twl[16 * 32];     // [d][lane] = exp(-2*pi*i*lane*d/512)

// ---------------------------------------------------------------------------
__global__ void prep_w(const float* __restrict__ vt, const float* __restrict__ stdv) {
    int i = blockIdx.x * 256 + threadIdx.x;
    if (i < CCH * CCH) {
        int d = i / CCH, c = i % CCH;
        g_Whi[i] = __float2half_rn(stdv[c] * vt[c * CCH + d]);
    }
}

__global__ void prep_tw(const float* __restrict__ kf) {
    int j = blockIdx.x * 256 + threadIdx.x;
    if (j < NFFT) {
        int kk = (j <= 256) ? j : (NFFT - j);
        g_kss[j] = kf[kk] * (1.0f / (float)NFFT);
        // g_twl[d][lane], j = d*32 + lane
        int d = j >> 5, l = j & 31;
        float s, c;
        sincospif(-(float)(l * d) * (1.0f / 256.0f), &s, &c);
        g_twl[j] = make_float2(c, s);
    }
}

// ---------------------------------------------------------------------------
// Warp-autonomous FFT-512 OA convolution.
// n = 32a + b (a = register slot 0..15, b = lane).
// fwd: FFT16 over a (regs) -> *W512^{bd} -> FFT32 over lanes (shfl, DIF ->
//      bitrev lane order). X[16*bitrev5(lane) + dr4(slot)] per (lane, slot).
// The last fwd butterfly (h=1), real spectrum diag, and first inv butterfly
// (h=1) are fused into Y = sc*v_self + pc*v_partner (one shfl pair).
// ---------------------------------------------------------------------------
__device__ __forceinline__ float2 cadd(float2 a, float2 b) { return make_float2(a.x+b.x, a.y+b.y); }
__device__ __forceinline__ float2 csub(float2 a, float2 b) { return make_float2(a.x-b.x, a.y-b.y); }
__device__ __forceinline__ float2 cmul(float2 a, float2 b) {
    return make_float2(fmaf(a.x, b.x, -a.y * b.y), fmaf(a.x, b.y, a.y * b.x));
}
__device__ __forceinline__ float2 cmulc(float2 a, float2 b) {  // a * conj(b)
    return make_float2(fmaf(a.x, b.x,  a.y * b.y), fmaf(a.y, b.x, -a.x * b.y));
}
__device__ __forceinline__ float2 shflx(float2 v, int m) {
    return make_float2(__shfl_xor_sync(0xffffffffu, v.x, m),
                       __shfl_xor_sync(0xffffffffu, v.y, m));
}
// forward radix-4 butterfly (W4 = -i), in place
__device__ __forceinline__ void fft4f(float2& p0, float2& p1, float2& p2, float2& p3) {
    float2 t0 = cadd(p0, p2), t1 = csub(p0, p2);
    float2 t2 = cadd(p1, p3), t3 = csub(p1, p3);
    p0 = cadd(t0, t2);
    p1 = make_float2(t1.x + t3.y, t1.y - t3.x);   // t1 - i*t3
    p2 = csub(t0, t2);
    p3 = make_float2(t1.x - t3.y, t1.y + t3.x);   // t1 + i*t3
}
// inverse radix-4 butterfly (W4 = +i)
__device__ __forceinline__ void ifft4f(float2& p0, float2& p1, float2& p2, float2& p3) {
    float2 t0 = cadd(p0, p2), t1 = csub(p0, p2);
    float2 t2 = cadd(p1, p3), t3 = csub(p1, p3);
    p0 = cadd(t0, t2);
    p1 = make_float2(t1.x - t3.y, t1.y + t3.x);   // t1 + i*t3
    p2 = csub(t0, t2);
    p3 = make_float2(t1.x + t3.y, t1.y - t3.x);   // t1 - i*t3
}

#define DR4(s) ((((s) & 3) << 2) | ((s) >> 2))

// W16 twiddle constants
#define TC1 0.92387953251128675613f
#define TS1 0.38268343236508977173f
#define TR2 0.70710678118654752440f

// multiply slot s by W16^{(s&3)*(s>>2)} (sign=+1 fwd, -1 inv via conj)
#define TW16(z, s, SGN) do {                                                   \
    const int _e = ((s) & 3) * ((s) >> 2);                                     \
    if (_e == 1)      z[s] = cmul(z[s], make_float2(TC1, (SGN) * -TS1));       \
    else if (_e == 2) z[s] = cmul(z[s], make_float2(TR2, (SGN) * -TR2));       \
    else if (_e == 3) z[s] = cmul(z[s], make_float2(TS1, (SGN) * -TC1));       \
    else if (_e == 4) z[s] = cmul(z[s], make_float2(0.0f, (SGN) * -1.0f));     \
    else if (_e == 6) z[s] = cmul(z[s], make_float2(-TR2, (SGN) * -TR2));      \
    else if (_e == 9) z[s] = cmul(z[s], make_float2(-TC1, (SGN) * TS1));       \
} while (0)

__global__ __launch_bounds__(128) void conv_warp(const float* __restrict__ noise)
{
    __shared__ float2 cbuf[4][2][120];

    const int lane = threadIdx.x & 31;
    const int w    = threadIdx.x >> 5;
    const int ch   = blockIdx.x;                 // 0..23
    const int pr   = blockIdx.y * 4 + w;         // row pair 0..383
    const int row0 = 2 * pr, row1 = row0 + 1;

    const float* n0 = noise + (size_t)row0 * TPAD;
    const float* n1 = noise + (size_t)row1 * TPAD;
    const size_t r0y = (size_t)row0 * TOUT;
    const size_t r1y = (size_t)row1 * TOUT;

    // ---- per-warp setup ----
    const int rb = __brev((unsigned)lane) >> 27;     // bitrev5(lane)
    // fused h1/spectrum/h1 coefficients: sc = k_self + k_partner,
    // pc = +-(k_e - k_o). Partner lane = lane^1 -> rb^16.
    float sc[16], pc[16];
    #pragma unroll
    for (int s = 0; s < 16; s++) {
        float kself = g_kss[16 * rb + DR4(s)];
        float kpart = g_kss[16 * (rb ^ 16) + DR4(s)];
        sc[s] = kself + kpart;
        pc[s] = (lane & 1) ? (kpart - kself) : (kself - kpart);
    }

    float2 w32, w16, w8;   // forward DIF stage twiddles
    {
        float ss, cc;
        sincospif(-(float)(lane & 15) * (1.0f / 16.0f), &ss, &cc); w32 = make_float2(cc, ss);
        sincospif(-(float)(lane & 7)  * (1.0f / 8.0f),  &ss, &cc); w16 = make_float2(cc, ss);
        sincospif(-(float)(lane & 3)  * (1.0f / 4.0f),  &ss, &cc); w8  = make_float2(cc, ss);
    }

    for (int k = 0; k < BLKS; k++) {
        const int b    = ch * BLKS + k;
        const int base = b * HOP;

        // ---- load: slot a holds (x0[32a+b], x1[32a+b]) ----
        float2 z[16];
        #pragma unroll
        for (int a = 0; a <= 12; a++) {
            int j = 32 * a + lane;
            int p = base + j;
            bool ok = (j < HOP) && (p < TPAD);
            z[a] = ok ? make_float2(__ldg(n0 + p), __ldg(n1 + p))
                      : make_float2(0.f, 0.f);
        }
        z[13] = z[14] = z[15] = make_float2(0.f, 0.f);

        // ---- forward FFT16 over a ----
        #pragma unroll
        for (int a0 = 0; a0 < 4; a0++) fft4f(z[a0], z[a0+4], z[a0+8], z[a0+12]);
        #pragma unroll
        for (int s = 0; s < 16; s++) TW16(z, s, 1.0f);
        #pragma unroll
        for (int d0 = 0; d0 < 4; d0++) fft4f(z[4*d0], z[4*d0+1], z[4*d0+2], z[4*d0+3]);

        // ---- twiddle W512^{b*d} ----
        #pragma unroll
        for (int s = 1; s < 16; s++)
            z[s] = cmul(z[s], g_twl[DR4(s) * 32 + lane]);

        // ---- lane FFT32 (DIF) + fused[h1|spectrum|h1] + inverse (DIT) ----
        #pragma unroll
        for (int s = 0; s < 16; s++) {
            float2 v = z[s];
            float2 u, t;
            // fwd h=16
            u = shflx(v, 16);
            t = cmul(csub(u, v), w32);
            v = (lane & 16) ? t : cadd(v, u);
            // fwd h=8
            u = shflx(v, 8);
            t = cmul(csub(u, v), w16);
            v = (lane & 8) ? t : cadd(v, u);
            // fwd h=4
            u = shflx(v, 4);
            t = cmul(csub(u, v), w8);
            v = (lane & 4) ? t : cadd(v, u);
            // fwd h=2, tw = -i for odd lane
            u = shflx(v, 2);
            t = csub(u, v);
            if (lane & 1) t = make_float2(t.y, -t.x);
            v = (lane & 2) ? t : cadd(v, u);

            // fused: fwd h=1 + real spectrum diag + inv h=1
            u = shflx(v, 1);
            v.x = fmaf(sc[s], v.x, pc[s] * u.x);
            v.y = fmaf(sc[s], v.y, pc[s] * u.y);

            // inv h=2, pre-twiddle +i on lanes with (lane&3)==3
            t = ((lane & 3) == 3) ? make_float2(-v.y, v.x) : v;
            u = shflx(t, 2);
            v = (lane & 2) ? csub(u, t) : cadd(t, u);
            // inv h=4
            t = (lane & 4) ? cmulc(v, w8) : v;
            u = shflx(t, 4);
            v = (lane & 4) ? csub(u, t) : cadd(t, u);
            // inv h=8
            t = (lane & 8) ? cmulc(v, w16) : v;
            u = shflx(t, 8);
            v = (lane & 8) ? csub(u, t) : cadd(t, u);
            // inv h=16
            t = (lane & 16) ? cmulc(v, w32) : v;
            u = shflx(t, 16);
            v = (lane & 16) ? csub(u, t) : cadd(t, u);

            z[s] = v;
        }

        // ---- conj twiddle W512^{-b*d} ----
        #pragma unroll
        for (int s = 1; s < 16; s++)
            z[s] = cmulc(z[s], g_twl[DR4(s) * 32 + lane]);

        // ---- inverse FFT16 over d ----
        #pragma unroll
        for (int d0 = 0; d0 < 4; d0++) ifft4f(z[4*d0], z[4*d0+1], z[4*d0+2], z[4*d0+3]);
        #pragma unroll
        for (int s = 0; s < 16; s++) TW16(z, s, -1.0f);
        #pragma unroll
        for (int a0 = 0; a0 < 4; a0++) ifft4f(z[a0], z[a0+4], z[a0+8], z[a0+12]);
        // slot a now holds y sample j = 32a + lane (both rows)

        // ---- routed writeout with per-warp carry ----
        float2*       cw = cbuf[w][k & 1];
        const float2* cr = cbuf[w][(k & 1) ^ 1];

        // heads: slots 0..3 (j < 120)
        if (k == 0) {
            if (ch > 0) {
                #pragma unroll
                for (int a = 0; a < 4; a++) {
                    int j = 32 * a + lane;
                    if (j < S2 - 1) {
                        g_bh[row0][ch - 1][j] = z[a].x;
                        g_bh[row1][ch - 1][j] = z[a].y;
                    }
                }
            }
        } else {
            #pragma unroll
            for (int a = 0; a < 4; a++) {
                int j = 32 * a + lane;
                if (j < S2 - 1) {
                    float2 cv = cr[j];
                    int t = base + j - (S2 - 1);
                    g_yhi[r0y + t] = __float2half_rn(z[a].x + cv.x);
                    g_yhi[r1y + t] = __float2half_rn(z[a].y + cv.y);
                }
            }
        }
        // exclusive region: slots 3..12 (120 <= j < 392)
        #pragma unroll
        for (int a = 3; a <= 12; a++) {
            int j = 32 * a + lane;
            if (j >= S2 - 1 && j < HOP) {
                int t = base + j - (S2 - 1);
                if (t < TOUT) {
                    g_yhi[r0y + t] = __float2half_rn(z[a].x);
                    g_yhi[r1y + t] = __float2half_rn(z[a].y);
                }
            }
        }
        // tails: slots 12..15 (j >= 392)
        #pragma unroll
        for (int a = 12; a < 16; a++) {
            int j = 32 * a + lane;
            if (j >= HOP) {
                int idx = j - HOP;
                if (k < BLKS - 1) {
                    cw[idx] = z[a];
                } else if (ch < NCHUNK - 1) {
                    g_bt[row0][ch][idx] = z[a].x;
                    g_bt[row1][ch][idx] = z[a].y;
                }
            }
        }
        __syncwarp();
    }
}

// ---------------------------------------------------------------------------
// fixB: the 23 chunk-boundary strips per row (b = 7(s+1)-1). Round-12 shape.
// ---------------------------------------------------------------------------
__global__ __launch_bounds__(256) void fixB() {
    const int row = blockIdx.x;
    for (int idx = threadIdx.x; idx < NSTRIP * 120; idx += 256) {
        int sb = idx / 120;
        int i  = idx - sb * 120;
        int b  = BLKS * (sb + 1) - 1;
        float v = g_bt[row][sb][i] + g_bh[row][sb][i];
        size_t off = (size_t)row * TOUT + b * HOP + 272 + i;
        g_yhi[off] = __float2half_rn(v);
    }
}

// ---------------------------------------------------------------------------
// GEMM: fp16 tensor-core, single pass, BK=64, 3-stage cp.async (round-12 form:
// cp.async.ca, next-stage issue AFTER the MMA burst).
//   C[t][d] = sum_c y[c][t] * W[d][c]
// ---------------------------------------------------------------------------
#define BM 128
#define BN 128
#define BK 64
#define ASTRIDE (BM + 8)
#define BSTRIDE (BK + 8)
#define ABUF (BK * ASTRIDE)
#define BBUF (BN * BSTRIDE)
#define NSTAGE 3
#define GEMM_SMEM (NSTAGE * (ABUF + BBUF) * 2)   // 107520 bytes

__device__ __forceinline__ uint32_t smem_u32(const void* p) {
    return (uint32_t)__cvta_generic_to_shared(p);
}
__device__ __forceinline__ void cp16(void* dst, const void* src) {
    asm volatile("cp.async.ca.shared.global [%0], [%1], 16;\n"
                 :: "r"(smem_u32(dst)), "l"(src));
}
__device__ __forceinline__ void cp_commit() { asm volatile("cp.async.commit_group;\n"); }
__device__ __forceinline__ void cp_wait1()  { asm volatile("cp.async.wait_group 1;\n"); }

__device__ __forceinline__ void ldmT4(uint32_t* r, uint32_t addr) {
    asm volatile("ldmatrix.sync.aligned.m8n8.x4.trans.shared.b16 {%0,%1,%2,%3},[%4];\n"
                 : "=r"(r[0]), "=r"(r[1]), "=r"(r[2]), "=r"(r[3]) : "r"(addr));
}
__device__ __forceinline__ void ldmN4(uint32_t* r, uint32_t addr) {
    asm volatile("ldmatrix.sync.aligned.m8n8.x4.shared.b16 {%0,%1,%2,%3},[%4];\n"
                 : "=r"(r[0]), "=r"(r[1]), "=r"(r[2]), "=r"(r[3]) : "r"(addr));
}
__device__ __forceinline__ void mma16816(float* c, const uint32_t* a, const uint32_t* b) {
    asm volatile("mma.sync.aligned.m16n8k16.row.col.f32.f16.f16.f32 "
                 "{%0,%1,%2,%3},{%4,%5,%6,%7},{%8,%9},{%0,%1,%2,%3};\n"
                 : "+f"(c[0]), "+f"(c[1]), "+f"(c[2]), "+f"(c[3])
                 : "r"(a[0]), "r"(a[1]), "r"(a[2]), "r"(a[3]), "r"(b[0]), "r"(b[1]));
}

__global__ __launch_bounds__(256, 2) void gemm_fp16(float* __restrict__ out) {
    extern __shared__ __align__(16) unsigned char smem_raw[];
    __half* As = reinterpret_cast<__half*>(smem_raw);
    __half* Bs = As + NSTAGE * ABUF;

    const int tid  = threadIdx.x;
    const int lane = tid & 31;
    const int w    = tid >> 5;
    const int wm   = w & 1;
    const int wn   = w >> 1;

    const int d0 = blockIdx.x * BN;
    const int t0 = blockIdx.y * BM;
    const int z  = blockIdx.z;

    auto issue = [&](int kt, int stg) {
        const int ksrc = kt * BK;
        const __half* Ag = g_yhi + ((size_t)(z * CCH + ksrc)) * TOUT + t0;
        const __half* Bg = g_Whi + (size_t)d0 * CCH + ksrc;
        __half* Asd = As + stg * ABUF;
        __half* Bsd = Bs + stg * BBUF;
        #pragma unroll
        for (int i = 0; i < 4; i++) {
            int cid = tid + 256 * i;
            int ka = cid >> 4, ma = (cid & 15) * 8;
            cp16(&Asd[ka * ASTRIDE + ma], Ag + (size_t)ka * TOUT + ma);
        }
        #pragma unroll
        for (int i = 0; i < 4; i++) {
            int cid = tid + 256 * i;
            int nb = cid >> 3, kb = (cid & 7) * 8;
            cp16(&Bsd[nb * BSTRIDE + kb], Bg + (size_t)nb * CCH + kb);
        }
    };

    const int g  = lane >> 3, r = lane & 7;
    const int ak = ((g & 2) << 2) + r;
    const int amo = (g & 1) << 3;
    const int bn = ((g & 2) << 2) + r;
    const int bko = (g & 1) << 3;

    const uint32_t as0 = smem_u32(As);
    const uint32_t bs0 = smem_u32(Bs);
    uint32_t aAddr[4], bAddr[2];
    #pragma unroll
    for (int mi = 0; mi < 4; mi++)
        aAddr[mi] = as0 + (uint32_t)((ak * ASTRIDE + wm * 64 + mi * 16 + amo) * 2);
    #pragma unroll
    for (int nj = 0; nj < 2; nj++)
        bAddr[nj] = bs0 + (uint32_t)(((wn * 32 + nj * 16 + bn) * BSTRIDE + bko) * 2);

    float acc[4][4][4];
    #pragma unroll
    for (int i = 0; i < 4; i++)
        #pragma unroll
        for (int j = 0; j < 4; j++)
            #pragma unroll
            for (int k = 0; k < 4; k++) acc[i][j][k] = 0.f;

    const int NKT = 6;

    #pragma unroll
    for (int s = 0; s < NSTAGE - 1; s++) { issue(s, s); cp_commit(); }

    for (int kt = 0; kt < NKT; kt++) {
        cp_wait1();
        __syncthreads();

        const int stg = kt % NSTAGE;
        const uint32_t aob = (uint32_t)(stg * ABUF * 2);
        const uint32_t bob = (uint32_t)(stg * BBUF * 2);
        #pragma unroll
        for (int kh = 0; kh < 4; kh++) {
            uint32_t afr[4][4], bfr[2][4];
            #pragma unroll
            for (int mi = 0; mi < 4; mi++)
                ldmT4(afr[mi], aAddr[mi] + aob + (uint32_t)(kh * 16 * ASTRIDE * 2));
            #pragma unroll
            for (int nj = 0; nj < 2; nj++)
                ldmN4(bfr[nj], bAddr[nj] + bob + (uint32_t)(kh * 32));
            #pragma unroll
            for (int mi = 0; mi < 4; mi++)
                #pragma unroll
                for (int n8 = 0; n8 < 4; n8++)
                    mma16816(acc[mi][n8], afr[mi], &bfr[n8 >> 1][(n8 & 1) * 2]);
        }

        if (kt + NSTAGE - 1 < NKT) issue(kt + NSTAGE - 1, (kt + NSTAGE - 1) % NSTAGE);
        cp_commit();
    }

    // epilogue
    const int cm  = lane >> 2;
    const int cn2 = (lane & 3) << 1;
    #pragma unroll
    for (int mi = 0; mi < 4; mi++) {
        const int t = t0 + wm * 64 + mi * 16 + cm;
        float* orow = out + ((size_t)z * TOUT + t) * CCH + d0 + wn * 32 + cn2;
        #pragma unroll
        for (int n8 = 0; n8 < 4; n8++) {
            float* o1 = orow + n8 * 8;
            *(float2*)o1             = make_float2(acc[mi][n8][0], acc[mi][n8][1]);
            *(float2*)(o1 + 8 * CCH) = make_float2(acc[mi][n8][2], acc[mi][n8][3]);
        }
    }
}

// ---------------------------------------------------------------------------
extern "C" void kernel_launch(void* const* d_in, const int* in_sizes, int n_in,
                              void* d_out, int out_size)
{
    const float* noise = (const float*)d_in[0];   // (768, 65656)
    const float* stdv  = (const float*)d_in[1];   // (384,)
    const float* vt    = (const float*)d_in[2];   // (384, 384)
    const float* kf    = (const float*)d_in[3];   // (257,)

    cudaFuncSetAttribute(gemm_fp16, cudaFuncAttributeMaxDynamicSharedMemorySize, GEMM_SMEM);

    prep_w<<<(CCH * CCH + 255) / 256, 256>>>(vt, stdv);
    prep_tw<<<2, 256>>>(kf);
    conv_warp<<<dim3(NCHUNK, 96), 128>>>(noise);
    fixB<<<NROWS, 256>>>();
    gemm_fp16<<<dim3(CCH / BN, TOUT / BM, 2), 256, GEMM_SMEM>>>((float*)d_out);
}

// round 17
// speedup vs baseline: 1.6209x; 1.6209x over previous
#include <cuda_runtime.h>
#include <cuda_fp16.h>
#include <cstdint>

// Problem constants
#define TPAD  65656      // t_padded = T_SIM + T_KERNEL - 1
#define TOUT  65536      // output time samples
#define CCH   384        // channels
#define NROWS 768        // SIZE * C
#define NB    168        // number of OA blocks
#define HOP   392        // BLOCK - s2 + 1
#define S2    121        // kernel length
#define NFFT  512        // OA block size
#define NCHUNK 24
#define BLKS  7          // blocks per chunk: 24*7 = 168
#define NSTRIP (NCHUNK - 1)   // 23 boundary strips per row

// fp16 filtered signal y[row][t]
__device__ __align__(256) __half g_yhi[(size_t)NROWS * TOUT];
// chunk-boundary strip contributions
__device__ float g_bt[NROWS][NSTRIP][120];    // tail of block 7(s+1)-1
__device__ float g_bh[NROWS][NSTRIP][120];    // head of block 7(s+1)
// Precomputed W[d][c] = std[c]*vt[c][d] in fp16
__device__ __align__(256) __half g_Whi[CCH * CCH];
// FFT tables
__device__ float  g_kss[NFFT];        // symmetric-extended kernel_fft / 512
__device__ float2 g_twl[16 * 32];     // [d][lane] = exp(-2*pi*i*lane*d/512)

// ---------------------------------------------------------------------------
__global__ void prep_w(const float* __restrict__ vt, const float* __restrict__ stdv) {
    int i = blockIdx.x * 256 + threadIdx.x;
    if (i < CCH * CCH) {
        int d = i / CCH, c = i % CCH;
        g_Whi[i] = __float2half_rn(stdv[c] * vt[c * CCH + d]);
    }
}

__global__ void prep_tw(const float* __restrict__ kf) {
    int j = blockIdx.x * 256 + threadIdx.x;
    if (j < NFFT) {
        int kk = (j <= 256) ? j : (NFFT - j);
        g_kss[j] = kf[kk] * (1.0f / (float)NFFT);
        // g_twl[d][lane], j = d*32 + lane
        int d = j >> 5, l = j & 31;
        float s, c;
        sincospif(-(float)(l * d) * (1.0f / 256.0f), &s, &c);
        g_twl[j] = make_float2(c, s);
    }
}

// ---------------------------------------------------------------------------
// Warp-autonomous FFT-512 OA convolution.
// n = 32a + b (a = register slot 0..15, b = lane).
// fwd: FFT16 over a (regs) -> *W512^{bd} -> FFT32 over lanes (shfl, DIF ->
//      bitrev lane order). X[16*bitrev5(lane) + dr4(slot)] per (lane, slot).
// spectrum multiply in that order; inverse mirrors back to natural (a,b).
// ---------------------------------------------------------------------------
__device__ __forceinline__ float2 cadd(float2 a, float2 b) { return make_float2(a.x+b.x, a.y+b.y); }
__device__ __forceinline__ float2 csub(float2 a, float2 b) { return make_float2(a.x-b.x, a.y-b.y); }
__device__ __forceinline__ float2 cmul(float2 a, float2 b) {
    return make_float2(fmaf(a.x, b.x, -a.y * b.y), fmaf(a.x, b.y, a.y * b.x));
}
__device__ __forceinline__ float2 cmulc(float2 a, float2 b) {  // a * conj(b)
    return make_float2(fmaf(a.x, b.x,  a.y * b.y), fmaf(a.y, b.x, -a.x * b.y));
}
__device__ __forceinline__ float2 shflx(float2 v, int m) {
    return make_float2(__shfl_xor_sync(0xffffffffu, v.x, m),
                       __shfl_xor_sync(0xffffffffu, v.y, m));
}
// forward radix-4 butterfly (W4 = -i), in place
__device__ __forceinline__ void fft4f(float2& p0, float2& p1, float2& p2, float2& p3) {
    float2 t0 = cadd(p0, p2), t1 = csub(p0, p2);
    float2 t2 = cadd(p1, p3), t3 = csub(p1, p3);
    p0 = cadd(t0, t2);
    p1 = make_float2(t1.x + t3.y, t1.y - t3.x);   // t1 - i*t3
    p2 = csub(t0, t2);
    p3 = make_float2(t1.x - t3.y, t1.y + t3.x);   // t1 + i*t3
}
// inverse radix-4 butterfly (W4 = +i)
__device__ __forceinline__ void ifft4f(float2& p0, float2& p1, float2& p2, float2& p3) {
    float2 t0 = cadd(p0, p2), t1 = csub(p0, p2);
    float2 t2 = cadd(p1, p3), t3 = csub(p1, p3);
    p0 = cadd(t0, t2);
    p1 = make_float2(t1.x - t3.y, t1.y + t3.x);   // t1 + i*t3
    p2 = csub(t0, t2);
    p3 = make_float2(t1.x + t3.y, t1.y - t3.x);   // t1 - i*t3
}

#define DR4(s) ((((s) & 3) << 2) | ((s) >> 2))

// W16 twiddle constants
#define TC1 0.92387953251128675613f
#define TS1 0.38268343236508977173f
#define TR2 0.70710678118654752440f

// multiply slot s by W16^{(s&3)*(s>>2)} (sign=+1 fwd, -1 inv via conj)
#define TW16(z, s, SGN) do {                                                   \
    const int _e = ((s) & 3) * ((s) >> 2);                                     \
    if (_e == 1)      z[s] = cmul(z[s], make_float2(TC1, (SGN) * -TS1));       \
    else if (_e == 2) z[s] = cmul(z[s], make_float2(TR2, (SGN) * -TR2));       \
    else if (_e == 3) z[s] = cmul(z[s], make_float2(TS1, (SGN) * -TC1));       \
    else if (_e == 4) z[s] = cmul(z[s], make_float2(0.0f, (SGN) * -1.0f));     \
    else if (_e == 6) z[s] = cmul(z[s], make_float2(-TR2, (SGN) * -TR2));      \
    else if (_e == 9) z[s] = cmul(z[s], make_float2(-TC1, (SGN) * TS1));       \
} while (0)

__global__ __launch_bounds__(128) void conv_warp(const float* __restrict__ noise)
{
    __shared__ float2 cbuf[4][2][120];

    const int lane = threadIdx.x & 31;
    const int w    = threadIdx.x >> 5;
    const int ch   = blockIdx.x;                 // 0..23
    const int pr   = blockIdx.y * 4 + w;         // row pair 0..383
    const int row0 = 2 * pr, row1 = row0 + 1;

    const float* n0 = noise + (size_t)row0 * TPAD;
    const float* n1 = noise + (size_t)row1 * TPAD;
    const size_t r0y = (size_t)row0 * TOUT;
    const size_t r1y = (size_t)row1 * TOUT;

    // ---- per-warp setup (lane-dependent constants) ----
    const int rb = __brev((unsigned)lane) >> 27;     // bitrev5(lane)
    float kssr[16];
    #pragma unroll
    for (int s = 0; s < 16; s++) kssr[s] = g_kss[16 * rb + DR4(s)];

    float2 w32, w16, w8;   // forward DIF stage twiddles
    {
        float ss, cc;
        sincospif(-(float)(lane & 15) * (1.0f / 16.0f), &ss, &cc); w32 = make_float2(cc, ss);
        sincospif(-(float)(lane & 7)  * (1.0f / 8.0f),  &ss, &cc); w16 = make_float2(cc, ss);
        sincospif(-(float)(lane & 3)  * (1.0f / 4.0f),  &ss, &cc); w8  = make_float2(cc, ss);
    }

    for (int k = 0; k < BLKS; k++) {
        const int b    = ch * BLKS + k;
        const int base = b * HOP;

        // ---- load: slot a holds (x0[32a+b], x1[32a+b]) ----
        float2 z[16];
        #pragma unroll
        for (int a = 0; a <= 12; a++) {
            int j = 32 * a + lane;
            int p = base + j;
            bool ok = (j < HOP) && (p < TPAD);
            z[a] = ok ? make_float2(__ldg(n0 + p), __ldg(n1 + p))
                      : make_float2(0.f, 0.f);
        }
        z[13] = z[14] = z[15] = make_float2(0.f, 0.f);

        // ---- forward FFT16 over a: inner (stride 4), twiddle, outer (consec) ----
        #pragma unroll
        for (int a0 = 0; a0 < 4; a0++) fft4f(z[a0], z[a0+4], z[a0+8], z[a0+12]);
        #pragma unroll
        for (int s = 0; s < 16; s++) TW16(z, s, 1.0f);
        #pragma unroll
        for (int d0 = 0; d0 < 4; d0++) fft4f(z[4*d0], z[4*d0+1], z[4*d0+2], z[4*d0+3]);
        // slot s now holds Y[b][dr4(s)]

        // ---- twiddle W512^{b*d} ----
        #pragma unroll
        for (int s = 1; s < 16; s++)
            z[s] = cmul(z[s], g_twl[DR4(s) * 32 + lane]);

        // ---- forward FFT32 across lanes (DIF), + spectrum, + inverse FFT32 (DIT) ----
        #pragma unroll
        for (int s = 0; s < 16; s++) {
            float2 v = z[s];
            float2 u, t;
            // fwd h=16
            u = shflx(v, 16);
            t = cmul(csub(u, v), w32);
            v = (lane & 16) ? t : cadd(v, u);
            // fwd h=8
            u = shflx(v, 8);
            t = cmul(csub(u, v), w16);
            v = (lane & 8) ? t : cadd(v, u);
            // fwd h=4
            u = shflx(v, 4);
            t = cmul(csub(u, v), w8);
            v = (lane & 4) ? t : cadd(v, u);
            // fwd h=2, tw = -i for odd lane
            u = shflx(v, 2);
            t = csub(u, v);
            if (lane & 1) t = make_float2(t.y, -t.x);
            v = (lane & 2) ? t : cadd(v, u);
            // fwd h=1
            u = shflx(v, 1);
            v = (lane & 1) ? csub(u, v) : cadd(v, u);

            // spectrum multiply (bitrev lane order, dr4 slot order)
            v.x *= kssr[s]; v.y *= kssr[s];

            // inv h=1
            u = shflx(v, 1);
            v = (lane & 1) ? csub(u, v) : cadd(v, u);
            // inv h=2, pre-twiddle +i on lanes with (lane&3)==3
            t = ((lane & 3) == 3) ? make_float2(-v.y, v.x) : v;
            u = shflx(t, 2);
            v = (lane & 2) ? csub(u, t) : cadd(t, u);
            // inv h=4
            t = (lane & 4) ? cmulc(v, w8) : v;
            u = shflx(t, 4);
            v = (lane & 4) ? csub(u, t) : cadd(t, u);
            // inv h=8
            t = (lane & 8) ? cmulc(v, w16) : v;
            u = shflx(t, 8);
            v = (lane & 8) ? csub(u, t) : cadd(t, u);
            // inv h=16
            t = (lane & 16) ? cmulc(v, w32) : v;
            u = shflx(t, 16);
            v = (lane & 16) ? csub(u, t) : cadd(t, u);

            z[s] = v;
        }

        // ---- conj twiddle W512^{-b*d} ----
        #pragma unroll
        for (int s = 1; s < 16; s++)
            z[s] = cmulc(z[s], g_twl[DR4(s) * 32 + lane]);

        // ---- inverse FFT16 over d: inner (consec), conj twiddle, outer (stride 4) ----
        #pragma unroll
        for (int d0 = 0; d0 < 4; d0++) ifft4f(z[4*d0], z[4*d0+1], z[4*d0+2], z[4*d0+3]);
        #pragma unroll
        for (int s = 0; s < 16; s++) TW16(z, s, -1.0f);
        #pragma unroll
        for (int a0 = 0; a0 < 4; a0++) ifft4f(z[a0], z[a0+4], z[a0+8], z[a0+12]);
        // slot a now holds y sample j = 32a + lane (both rows)

        // ---- routed writeout with per-warp carry ----
        float2*       cw = cbuf[w][k & 1];
        const float2* cr = cbuf[w][(k & 1) ^ 1];

        // heads: slots 0..3 (j < 120)
        if (k == 0) {
            if (ch > 0) {
                #pragma unroll
                for (int a = 0; a < 4; a++) {
                    int j = 32 * a + lane;
                    if (j < S2 - 1) {
                        g_bh[row0][ch - 1][j] = z[a].x;
                        g_bh[row1][ch - 1][j] = z[a].y;
                    }
                }
            }
        } else {
            #pragma unroll
            for (int a = 0; a < 4; a++) {
                int j = 32 * a + lane;
                if (j < S2 - 1) {
                    float2 cv = cr[j];
                    int t = base + j - (S2 - 1);
                    g_yhi[r0y + t] = __float2half_rn(z[a].x + cv.x);
                    g_yhi[r1y + t] = __float2half_rn(z[a].y + cv.y);
                }
            }
        }
        // exclusive region: slots 3..12 (120 <= j < 392)
        #pragma unroll
        for (int a = 3; a <= 12; a++) {
            int j = 32 * a + lane;
            if (j >= S2 - 1 && j < HOP) {
                int t = base + j - (S2 - 1);
                if (t < TOUT) {
                    g_yhi[r0y + t] = __float2half_rn(z[a].x);
                    g_yhi[r1y + t] = __float2half_rn(z[a].y);
                }
            }
        }
        // tails: slots 12..15 (j >= 392)
        #pragma unroll
        for (int a = 12; a < 16; a++) {
            int j = 32 * a + lane;
            if (j >= HOP) {
                int idx = j - HOP;
                if (k < BLKS - 1) {
                    cw[idx] = z[a];
                } else if (ch < NCHUNK - 1) {
                    g_bt[row0][ch][idx] = z[a].x;
                    g_bt[row1][ch][idx] = z[a].y;
                }
            }
        }
        __syncwarp();
    }
}

// ---------------------------------------------------------------------------
// fixB: the 23 chunk-boundary strips per row (b = 7(s+1)-1).
// ---------------------------------------------------------------------------
__global__ __launch_bounds__(256) void fixB() {
    const int row = blockIdx.x;
    for (int idx = threadIdx.x; idx < NSTRIP * 120; idx += 256) {
        int sb = idx / 120;
        int i  = idx - sb * 120;
        int b  = BLKS * (sb + 1) - 1;
        float v = g_bt[row][sb][i] + g_bh[row][sb][i];
        size_t off = (size_t)row * TOUT + b * HOP + 272 + i;
        g_yhi[off] = __float2half_rn(v);
    }
}

// ---------------------------------------------------------------------------
// GEMM: fp16 tensor-core, single pass, BK=64, 3-stage cp.async (unchanged).
//   C[t][d] = sum_c y[c][t] * W[d][c]
// ---------------------------------------------------------------------------
#define BM 128
#define BN 128
#define BK 64
#define ASTRIDE (BM + 8)
#define BSTRIDE (BK + 8)
#define ABUF (BK * ASTRIDE)
#define BBUF (BN * BSTRIDE)
#define NSTAGE 3
#define GEMM_SMEM (NSTAGE * (ABUF + BBUF) * 2)   // 107520 bytes

__device__ __forceinline__ uint32_t smem_u32(const void* p) {
    return (uint32_t)__cvta_generic_to_shared(p);
}
__device__ __forceinline__ void cp16(void* dst, const void* src) {
    asm volatile("cp.async.ca.shared.global [%0], [%1], 16;\n"
                 :: "r"(smem_u32(dst)), "l"(src));
}
__device__ __forceinline__ void cp_commit() { asm volatile("cp.async.commit_group;\n"); }
__device__ __forceinline__ void cp_wait1()  { asm volatile("cp.async.wait_group 1;\n"); }

__device__ __forceinline__ void ldmT4(uint32_t* r, uint32_t addr) {
    asm volatile("ldmatrix.sync.aligned.m8n8.x4.trans.shared.b16 {%0,%1,%2,%3},[%4];\n"
                 : "=r"(r[0]), "=r"(r[1]), "=r"(r[2]), "=r"(r[3]) : "r"(addr));
}
__device__ __forceinline__ void ldmN4(uint32_t* r, uint32_t addr) {
    asm volatile("ldmatrix.sync.aligned.m8n8.x4.shared.b16 {%0,%1,%2,%3},[%4];\n"
                 : "=r"(r[0]), "=r"(r[1]), "=r"(r[2]), "=r"(r[3]) : "r"(addr));
}
__device__ __forceinline__ void mma16816(float* c, const uint32_t* a, const uint32_t* b) {
    asm volatile("mma.sync.aligned.m16n8k16.row.col.f32.f16.f16.f32 "
                 "{%0,%1,%2,%3},{%4,%5,%6,%7},{%8,%9},{%0,%1,%2,%3};\n"
                 : "+f"(c[0]), "+f"(c[1]), "+f"(c[2]), "+f"(c[3])
                 : "r"(a[0]), "r"(a[1]), "r"(a[2]), "r"(a[3]), "r"(b[0]), "r"(b[1]));
}

__global__ __launch_bounds__(256, 2) void gemm_fp16(float* __restrict__ out) {
    extern __shared__ __align__(16) unsigned char smem_raw[];
    __half* As = reinterpret_cast<__half*>(smem_raw);
    __half* Bs = As + NSTAGE * ABUF;

    const int tid  = threadIdx.x;
    const int lane = tid & 31;
    const int w    = tid >> 5;
    const int wm   = w & 1;
    const int wn   = w >> 1;

    const int d0 = blockIdx.x * BN;
    const int t0 = blockIdx.y * BM;
    const int z  = blockIdx.z;

    auto issue = [&](int kt, int stg) {
        const int ksrc = kt * BK;
        const __half* Ag = g_yhi + ((size_t)(z * CCH + ksrc)) * TOUT + t0;
        const __half* Bg = g_Whi + (size_t)d0 * CCH + ksrc;
        __half* Asd = As + stg * ABUF;
        __half* Bsd = Bs + stg * BBUF;
        #pragma unroll
        for (int i = 0; i < 4; i++) {
            int cid = tid + 256 * i;
            int ka = cid >> 4, ma = (cid & 15) * 8;
            cp16(&Asd[ka * ASTRIDE + ma], Ag + (size_t)ka * TOUT + ma);
        }
        #pragma unroll
        for (int i = 0; i < 4; i++) {
            int cid = tid + 256 * i;
            int nb = cid >> 3, kb = (cid & 7) * 8;
            cp16(&Bsd[nb * BSTRIDE + kb], Bg + (size_t)nb * CCH + kb);
        }
    };

    const int g  = lane >> 3, r = lane & 7;
    const int ak = ((g & 2) << 2) + r;
    const int amo = (g & 1) << 3;
    const int bn = ((g & 2) << 2) + r;
    const int bko = (g & 1) << 3;

    const uint32_t as0 = smem_u32(As);
    const uint32_t bs0 = smem_u32(Bs);
    uint32_t aAddr[4], bAddr[2];
    #pragma unroll
    for (int mi = 0; mi < 4; mi++)
        aAddr[mi] = as0 + (uint32_t)((ak * ASTRIDE + wm * 64 + mi * 16 + amo) * 2);
    #pragma unroll
    for (int nj = 0; nj < 2; nj++)
        bAddr[nj] = bs0 + (uint32_t)(((wn * 32 + nj * 16 + bn) * BSTRIDE + bko) * 2);

    float acc[4][4][4];
    #pragma unroll
    for (int i = 0; i < 4; i++)
        #pragma unroll
        for (int j = 0; j < 4; j++)
            #pragma unroll
            for (int k = 0; k < 4; k++) acc[i][j][k] = 0.f;

    const int NKT = 6;

    #pragma unroll
    for (int s = 0; s < NSTAGE - 1; s++) { issue(s, s); cp_commit(); }

    for (int kt = 0; kt < NKT; kt++) {
        cp_wait1();
        __syncthreads();

        const int stg = kt % NSTAGE;
        const uint32_t aob = (uint32_t)(stg * ABUF * 2);
        const uint32_t bob = (uint32_t)(stg * BBUF * 2);
        #pragma unroll
        for (int kh = 0; kh < 4; kh++) {
            uint32_t afr[4][4], bfr[2][4];
            #pragma unroll
            for (int mi = 0; mi < 4; mi++)
                ldmT4(afr[mi], aAddr[mi] + aob + (uint32_t)(kh * 16 * ASTRIDE * 2));
            #pragma unroll
            for (int nj = 0; nj < 2; nj++)
                ldmN4(bfr[nj], bAddr[nj] + bob + (uint32_t)(kh * 32));
            #pragma unroll
            for (int mi = 0; mi < 4; mi++)
                #pragma unroll
                for (int n8 = 0; n8 < 4; n8++)
                    mma16816(acc[mi][n8], afr[mi], &bfr[n8 >> 1][(n8 & 1) * 2]);
        }

        if (kt + NSTAGE - 1 < NKT) issue(kt + NSTAGE - 1, (kt + NSTAGE - 1) % NSTAGE);
        cp_commit();
    }

    // epilogue
    const int cm  = lane >> 2;
    const int cn2 = (lane & 3) << 1;
    #pragma unroll
    for (int mi = 0; mi < 4; mi++) {
        const int t = t0 + wm * 64 + mi * 16 + cm;
        float* orow = out + ((size_t)z * TOUT + t) * CCH + d0 + wn * 32 + cn2;
        #pragma unroll
        for (int n8 = 0; n8 < 4; n8++) {
            float* o1 = orow + n8 * 8;
            *(float2*)o1             = make_float2(acc[mi][n8][0], acc[mi][n8][1]);
            *(float2*)(o1 + 8 * CCH) = make_float2(acc[mi][n8][2], acc[mi][n8][3]);
        }
    }
}

// ---------------------------------------------------------------------------
extern "C" void kernel_launch(void* const* d_in, const int* in_sizes, int n_in,
                              void* d_out, int out_size)
{
    const float* noise = (const float*)d_in[0];   // (768, 65656)
    const float* stdv  = (const float*)d_in[1];   // (384,)
    const float* vt    = (const float*)d_in[2];   // (384, 384)
    const float* kf    = (const float*)d_in[3];   // (257,)

    cudaFuncSetAttribute(gemm_fp16, cudaFuncAttributeMaxDynamicSharedMemorySize, GEMM_SMEM);

    prep_w<<<(CCH * CCH + 255) / 256, 256>>>(vt, stdv);
    prep_tw<<<2, 256>>>(kf);
    conv_warp<<<dim3(NCHUNK, 96), 128>>>(noise);
    fixB<<<NROWS, 256>>>();
    gemm_fp16<<<dim3(CCH / BN, TOUT / BM, 2), 256, GEMM_SMEM>>>((float*)d_out);
}